// round 3
// baseline (speedup 1.0000x reference)
#include <cuda_runtime.h>
#include <cuda_bf16.h>

// CALayer (squeeze-excitation), fused single-pass.
// x:[16,256,128,128] f32. Each block owns one [128,128] plane, keeps it in
// 64KB dynamic smem: (1) sum plane -> publish mean, (2) spin until all 256
// planes of its batch published, (3) redundantly compute the tiny SE MLP,
// (4) scale the smem-resident plane and stream-store to out.
// x is read from HBM exactly ONCE: traffic 805MB -> 537MB.

#define BATCH 16
#define CHAN 256
#define CR 16
#define HW 16384               // 128*128 floats = 64KB
#define NPLANES (BATCH*CHAN)   // 4096

__device__ float g_mean[NPLANES];
__device__ int   g_cnt[BATCH];

__global__ void init_kernel() {
    if (threadIdx.x < BATCH) g_cnt[threadIdx.x] = 0;
}

__device__ __forceinline__ void stcs4(float4* p, float4 v) {
    asm volatile("st.global.cs.v4.f32 [%0], {%1,%2,%3,%4};"
                 :: "l"(p), "f"(v.x), "f"(v.y), "f"(v.z), "f"(v.w) : "memory");
}

__global__ __launch_bounds__(256, 3) void fused_se_kernel(
    const float* __restrict__ x, float* __restrict__ out,
    const float* __restrict__ w1, const float* __restrict__ b1,
    const float* __restrict__ w2, const float* __restrict__ b2)
{
    extern __shared__ float splane[];   // HW floats = 64KB
    __shared__ float sred[8];
    __shared__ float smean[CHAN];
    __shared__ float shid[CR];
    __shared__ float sscale;

    const int p   = blockIdx.x;
    const int b   = p >> 8;       // batch
    const int c   = p & 255;      // channel
    const int tid = threadIdx.x;

    // ---- Pass 1: load plane into smem, accumulate sum ----
    float4* sp4 = reinterpret_cast<float4*>(splane);
    const float4* __restrict__ xp =
        reinterpret_cast<const float4*>(x + (size_t)p * HW);
    float s = 0.f;
    #pragma unroll
    for (int i = 0; i < 16; i++) {
        float4 v = __ldg(&xp[tid + i * 256]);
        sp4[tid + i * 256] = v;
        s += (v.x + v.y) + (v.z + v.w);
    }
    #pragma unroll
    for (int o = 16; o > 0; o >>= 1) s += __shfl_xor_sync(0xFFFFFFFF, s, o);
    if ((tid & 31) == 0) sred[tid >> 5] = s;
    __syncthreads();

    // ---- Publish mean, arrive at batch counter ----
    if (tid == 0) {
        float t = 0.f;
        #pragma unroll
        for (int w = 0; w < 8; w++) t += sred[w];
        g_mean[p] = t * (1.0f / HW);
        __threadfence();
        atomicAdd(&g_cnt[b], 1);
    }

    // ---- Spin until the whole batch has published ----
    if (tid == 0) {
        while (atomicAdd(&g_cnt[b], 0) < CHAN) {
            __nanosleep(128);
        }
    }
    __syncthreads();
    __threadfence();

    // ---- Read batch means (L2-fresh) ----
    smean[tid] = __ldcg(&g_mean[b * CHAN + tid]);
    __syncthreads();

    // ---- Tiny MLP (redundant per block; weights hit L2) ----
    if (tid < CR) {
        float acc = b1[tid];
        #pragma unroll 8
        for (int k = 0; k < CHAN; k++)
            acc += w1[tid * CHAN + k] * smean[k];
        shid[tid] = fmaxf(acc, 0.f);
    }
    __syncthreads();
    if (tid == 0) {
        float acc = b2[c];
        #pragma unroll
        for (int r = 0; r < CR; r++)
            acc += w2[c * CR + r] * shid[r];
        sscale = 1.0f / (1.0f + __expf(-acc));
    }
    __syncthreads();

    // ---- Pass 2: scale smem plane, stream to gmem ----
    const float sc = sscale;
    float4* __restrict__ op = reinterpret_cast<float4*>(out + (size_t)p * HW);
    #pragma unroll
    for (int i = 0; i < 16; i++) {
        const int idx = tid + i * 256;
        float4 v = sp4[idx];
        v.x *= sc; v.y *= sc; v.z *= sc; v.w *= sc;
        stcs4(&op[idx], v);
    }
}

extern "C" void kernel_launch(void* const* d_in, const int* in_sizes, int n_in,
                              void* d_out, int out_size) {
    const float* x  = (const float*)d_in[0];
    const float* w1 = (const float*)d_in[1];
    const float* b1 = (const float*)d_in[2];
    const float* w2 = (const float*)d_in[3];
    const float* b2 = (const float*)d_in[4];
    float* out = (float*)d_out;

    static_assert(HW * sizeof(float) == 65536, "plane size");
    cudaFuncSetAttribute(fused_se_kernel,
                         cudaFuncAttributeMaxDynamicSharedMemorySize,
                         HW * sizeof(float));

    init_kernel<<<1, 32>>>();
    fused_se_kernel<<<NPLANES, 256, HW * sizeof(float)>>>(x, out, w1, b1, w2, b2);
}

// round 4
// speedup vs baseline: 2.1623x; 2.1623x over previous
#include <cuda_runtime.h>
#include <cuda_bf16.h>

// CALayer SE, single-pass persistent kernel.
// 512 co-resident blocks (guaranteed: launch_bounds(256,4) -> 4 blocks/SM x 148
// = 592 slots >= 512), 16 rounds (one batch each). Per round a block reads a
// 32KB half-plane chunk into REGISTERS (8 x float4/thread), publishes its
// partial sum, spins on a per-batch counter (deadlock-free since all blocks
// resident), computes the tiny MLP redundantly, then scales the register-held
// data and streams it out. x read once: 537MB total HBM traffic.

#define BATCH 16
#define CHAN 256
#define CR 16
#define HW 16384               // floats per plane
#define NPLANES (BATCH*CHAN)
#define NBLK 512
#define TPB 256
#define PLANE_F4 (HW/4)        // 4096
#define HALF_F4 (HW/8)         // 2048

__device__ float g_part[NPLANES * 2];
__device__ int   g_cnt[BATCH];

__global__ void init_kernel() {
    if (threadIdx.x < BATCH) g_cnt[threadIdx.x] = 0;
}

__device__ __forceinline__ float4 ldcs4(const float4* p) {
    float4 v;
    asm volatile("ld.global.cs.v4.f32 {%0,%1,%2,%3}, [%4];"
                 : "=f"(v.x), "=f"(v.y), "=f"(v.z), "=f"(v.w) : "l"(p));
    return v;
}
__device__ __forceinline__ void stcs4(float4* p, float4 v) {
    asm volatile("st.global.cs.v4.f32 [%0], {%1,%2,%3,%4};"
                 :: "l"(p), "f"(v.x), "f"(v.y), "f"(v.z), "f"(v.w) : "memory");
}

__global__ __launch_bounds__(TPB, 4) void fused_se_kernel(
    const float* __restrict__ x, float* __restrict__ out,
    const float* __restrict__ w1, const float* __restrict__ b1,
    const float* __restrict__ w2, const float* __restrict__ b2)
{
    __shared__ float sred[8];
    __shared__ float smean[CHAN];
    __shared__ float shid[CR];
    __shared__ float sscale;

    const int plane_local = blockIdx.x >> 1;   // 0..255 (channel)
    const int half        = blockIdx.x & 1;    // 0..1
    const int tid  = threadIdx.x;
    const int lane = tid & 31;
    const int wid  = tid >> 5;

    for (int b = 0; b < BATCH; b++) {
        const int p = (b << 8) | plane_local;
        const float4* __restrict__ xp = reinterpret_cast<const float4*>(x)
            + (size_t)p * PLANE_F4 + (size_t)half * HALF_F4;

        // ---- Pass 1: stream chunk into registers, sum ----
        float4 v[8];
        #pragma unroll
        for (int i = 0; i < 8; i++) v[i] = ldcs4(&xp[tid + i * TPB]);
        float s = 0.f;
        #pragma unroll
        for (int i = 0; i < 8; i++) s += (v[i].x + v[i].y) + (v[i].z + v[i].w);
        #pragma unroll
        for (int o = 16; o; o >>= 1) s += __shfl_xor_sync(0xFFFFFFFF, s, o);
        if (lane == 0) sred[wid] = s;
        __syncthreads();

        // ---- Publish partial, barrier over all 512 blocks ----
        if (tid == 0) {
            float t = 0.f;
            #pragma unroll
            for (int w = 0; w < 8; w++) t += sred[w];
            g_part[p * 2 + half] = t;
            __threadfence();
            atomicAdd(&g_cnt[b], 1);
            while (atomicAdd(&g_cnt[b], 0) < NBLK) __nanosleep(100);
            __threadfence();
        }
        __syncthreads();

        // ---- Batch means (deterministic: fixed half0+half1 order) ----
        {
            const int q = ((b << 8) + tid) * 2;
            smean[tid] = (__ldcg(&g_part[q]) + __ldcg(&g_part[q + 1])) * (1.0f / HW);
        }
        __syncthreads();

        // ---- Hidden layer: 8 warps x 2 rows ----
        #pragma unroll
        for (int k = 0; k < 2; k++) {
            const int r = wid * 2 + k;
            float acc = 0.f;
            #pragma unroll
            for (int c = lane; c < CHAN; c += 32)
                acc += __ldg(&w1[r * CHAN + c]) * smean[c];
            #pragma unroll
            for (int o = 16; o; o >>= 1) acc += __shfl_xor_sync(0xFFFFFFFF, acc, o);
            if (lane == 0) shid[r] = fmaxf(acc + __ldg(&b1[r]), 0.f);
        }
        __syncthreads();

        // ---- Gate for this block's channel ----
        if (tid == 0) {
            float acc = __ldg(&b2[plane_local]);
            #pragma unroll
            for (int r = 0; r < CR; r++)
                acc += __ldg(&w2[plane_local * CR + r]) * shid[r];
            sscale = 1.0f / (1.0f + __expf(-acc));
        }
        __syncthreads();

        // ---- Pass 2: scale register-held data, stream out ----
        const float sc = sscale;
        float4* __restrict__ op = reinterpret_cast<float4*>(out)
            + (size_t)p * PLANE_F4 + (size_t)half * HALF_F4;
        #pragma unroll
        for (int i = 0; i < 8; i++) {
            float4 t4 = v[i];
            t4.x *= sc; t4.y *= sc; t4.z *= sc; t4.w *= sc;
            stcs4(&op[tid + i * TPB], t4);
        }
        __syncthreads();
    }
}

extern "C" void kernel_launch(void* const* d_in, const int* in_sizes, int n_in,
                              void* d_out, int out_size) {
    const float* x  = (const float*)d_in[0];
    const float* w1 = (const float*)d_in[1];
    const float* b1 = (const float*)d_in[2];
    const float* w2 = (const float*)d_in[3];
    const float* b2 = (const float*)d_in[4];
    float* out = (float*)d_out;

    init_kernel<<<1, 32>>>();
    fused_se_kernel<<<NBLK, TPB>>>(x, out, w1, b1, w2, b2);
}